// round 13
// baseline (speedup 1.0000x reference)
#include <cuda_runtime.h>

// Problem constants
#define BB   32
#define TT   400
#define DD   64
#define NBT  (BB*TT)      // 12800 matrices
#define S    68           // shared row stride (floats)
#define NB   8            // Cholesky block size

#define HALF_D_LOG_2PI 58.812066125098784f   // 0.5 * 64 * log(2*pi)
#define EPS 1e-6f

__device__ __align__(16) float g_partial[NBT];
__device__ double g_stage[25];
__device__ int    g_count;     // static-zero; last CTA resets each call

// Wide-phase row split for 224 worker threads: m2 = 49-8b rows.
// p = min(floor(224/m2),16); K = ceil(65536/p) for fixed-point div (exact for wt<256).
__constant__ int c_p[7] = {4, 5, 6, 8, 13, 16, 16};
__constant__ int c_K[7] = {16384, 13108, 10923, 8192, 5042, 4096, 4096};

// Panel factorization of 8 columns held TRANSPOSED+contiguous in P:
// P[kk*S + i] = A[i][b0+kk], rows i = b0..64 valid. One warp, conflict-free.
__device__ __forceinline__ float panel_fact(float* P, int b0, int lane)
{
    float logdet = 0.f;
    #pragma unroll
    for (int kk = 0; kk < NB; kk++) {
        const int k = b0 + kk;
        float d    = P[kk * S + k] + EPS;      // EPS folded at pivot read
        float invL = rsqrtf(d);
        if (lane == 0) logdet += 0.5f * __logf(d);

        for (int i = k + 1 + lane; i <= 64; i += 32)
            P[kk * S + i] *= invL;
        __syncwarp();

        float s[NB];
        #pragma unroll
        for (int jj = kk + 1; jj < NB; jj++) s[jj] = P[kk * S + b0 + jj];
        for (int i = k + 1 + lane; i <= 64; i += 32) {
            float li = P[kk * S + i];
            #pragma unroll
            for (int jj = kk + 1; jj < NB; jj++)
                P[jj * S + i] = fmaf(-li, s[jj], P[jj * S + i]);
        }
        __syncwarp();
    }
    return logdet;
}

// One CTA (256 threads) per matrix. Blocked Cholesky NB=8 with LOOKAHEAD on the
// bordered 65x64 system (row 64 = x-mu; corner accumulates -z.z).
// Per block b:
//   narrow(b): ALL warps apply panel-b rank-8 to the next 8-col block
//              (rows nx0..64, cols nx0..nx0+7) and write it transposed into Pn.
//   overlap:   warp (b+1) factorizes panel b+1 inside Pn (contiguous) WHILE the
//              other 7 warps apply panel-b rank-8 to cols >= nx0+8 ("wide").
// Regions are disjoint; per-element FMA order identical to the rank-8 baseline.
__global__ __launch_bounds__(256)
void chol_ll_kernel(const float* __restrict__ x,
                    const float* __restrict__ mu,
                    const float* __restrict__ sigma)
{
    __shared__ __align__(16) float sm[65 * S];
    __shared__ __align__(16) float Pt[2][NB * S];
    __shared__ float wlog[NB];

    const int bt   = blockIdx.x;
    const int tid  = threadIdx.x;
    const int lane = tid & 31;
    const int wid  = tid >> 5;

    // ---- Load sigma (float4 coalesced); fold cols 0..7 transposed into Pt[0] ----
    const float4* src = (const float4*)(sigma + (size_t)bt * (DD * DD));
    #pragma unroll
    for (int it = 0; it < 4; it++) {
        int idx = tid + it * 256;
        float4 v = src[idx];
        int r  = idx >> 4;
        int cb = (idx & 15) << 2;
        *(float4*)&sm[r * S + cb] = v;
        if (cb == 0) {
            Pt[0][0 * S + r] = v.x; Pt[0][1 * S + r] = v.y;
            Pt[0][2 * S + r] = v.z; Pt[0][3 * S + r] = v.w;
        } else if (cb == 4) {
            Pt[0][4 * S + r] = v.x; Pt[0][5 * S + r] = v.y;
            Pt[0][6 * S + r] = v.z; Pt[0][7 * S + r] = v.w;
        }
    }
    if (tid < DD) {
        float d = x[(size_t)bt * DD + tid] - mu[(size_t)bt * DD + tid];
        sm[64 * S + tid] = d;
        if (tid < NB) Pt[0][tid * S + 64] = d;   // border row of panel 0
    }
    if (tid == 64) sm[64 * S + 64] = 0.f;        // corner accumulator
    // Zero pads Pt[*][kk][65..67] once (border-chunk slack; never overwritten)
    if (tid >= 128 && tid < 176) {
        int t = tid - 128, buf = t / 24, rr = t % 24;
        Pt[buf][(rr / 3) * S + 65 + (rr % 3)] = 0.f;
    }
    __syncthreads();

    // ---- Panel 0 (nothing to overlap with) ----
    if (wid == 0) {
        float ld = panel_fact(Pt[0], 0, lane);
        if (lane == 0) wlog[0] = ld;
    }
    __syncthreads();

    #pragma unroll 1
    for (int b = 0; b < 8; b++) {
        float* Pc = Pt[b & 1];            // panel b (factorized)
        float* Pn = Pt[(b + 1) & 1];      // panel b+1 staging
        const int nx0 = 8 * b + 8;
        const int c0  = nx0 >> 2;

        // ==== narrow(b): rows nx0..64, chunks {c0, c0+1}; transpose into Pn ====
        const int mn = 65 - nx0;
        if (tid < 2 * mn) {
            int i = nx0 + (tid >> 1);
            int c = c0 + (tid & 1);
            if (c <= 16) {
                float4 a = *(float4*)&sm[i * S + 4 * c];
                #pragma unroll
                for (int kk = 0; kk < NB; kk++) {
                    float li  = Pc[kk * S + i];
                    float4 pk = *(const float4*)&Pc[kk * S + 4 * c];
                    a.x = fmaf(-li, pk.x, a.x);
                    a.y = fmaf(-li, pk.y, a.y);
                    a.z = fmaf(-li, pk.z, a.z);
                    a.w = fmaf(-li, pk.w, a.w);
                }
                *(float4*)&sm[i * S + 4 * c] = a;
                int jj = (tid & 1) << 2;            // 0 or 4
                Pn[(jj + 0) * S + i] = a.x;
                Pn[(jj + 1) * S + i] = a.y;
                Pn[(jj + 2) * S + i] = a.z;
                Pn[(jj + 3) * S + i] = a.w;
            }
        }
        __syncthreads();

        // ==== overlap: panel(b+1) on warp b+1  ||  wide(b) on the other 7 ====
        if (b < 7) {
            const int pw = b + 1;
            if (wid == pw) {
                float ld = panel_fact(Pn, nx0, lane);
                if (lane == 0) wlog[pw] = ld;
            } else {
                const int m2 = 49 - 8 * b;              // wide rows: nx0+8..64
                const int p  = c_p[b];
                const int K  = c_K[b];
                const int widx = (wid < pw) ? wid : wid - 1;   // 0..6
                const int wt   = widx * 32 + lane;             // 0..223
                if (wt < p * m2) {
                    const int r = (wt * K) >> 16;       // wt / p (exact)
                    const int h = wt - r * p;
                    const int i = nx0 + 8 + r;
                    float Li[NB];
                    #pragma unroll
                    for (int kk = 0; kk < NB; kk++) Li[kk] = Pc[kk * S + i];
                    const int ce = i >> 2;
                    for (int c = c0 + 2 + h; c <= ce; c += p) {
                        float4 a = *(float4*)&sm[i * S + 4 * c];
                        #pragma unroll
                        for (int kk = 0; kk < NB; kk++) {
                            float4 pk = *(const float4*)&Pc[kk * S + 4 * c];
                            a.x = fmaf(-Li[kk], pk.x, a.x);
                            a.y = fmaf(-Li[kk], pk.y, a.y);
                            a.z = fmaf(-Li[kk], pk.z, a.z);
                            a.w = fmaf(-Li[kk], pk.w, a.w);
                        }
                        *(float4*)&sm[i * S + 4 * c] = a;
                    }
                }
            }
            __syncthreads();
        }
    }

    // narrow(7) updated the corner; its trailing __syncthreads made it visible.
    if (tid == 0) {
        float ld = 0.f;
        #pragma unroll
        for (int w = 0; w < NB; w++) ld += wlog[w];
        g_partial[bt] = 0.5f * sm[64 * S + 64] - ld - HALF_D_LOG_2PI;
    }
}

// Single-launch deterministic reduction: 25 CTAs x 512 elems; last CTA (atomic
// ticket) sums the 25 stage values in FIXED order.
__global__ __launch_bounds__(128)
void reduce_ll_kernel(float* __restrict__ out)
{
    __shared__ double red[128];
    const float4 v = ((const float4*)g_partial)[blockIdx.x * 128 + threadIdx.x];
    red[threadIdx.x] = (double)v.x + (double)v.y + (double)v.z + (double)v.w;
    __syncthreads();
    #pragma unroll
    for (int s = 64; s > 0; s >>= 1) {
        if (threadIdx.x < s) red[threadIdx.x] += red[threadIdx.x + s];
        __syncthreads();
    }
    if (threadIdx.x == 0) {
        g_stage[blockIdx.x] = red[0];
        __threadfence();
        int done = atomicAdd(&g_count, 1);
        if (done == 24) {
            __threadfence();
            double t = 0.0;
            #pragma unroll
            for (int i = 0; i < 25; i++) t += g_stage[i];
            out[0] = (float)(-t / (double)BB);
            g_count = 0;   // reset for next graph replay
        }
    }
}

extern "C" void kernel_launch(void* const* d_in, const int* in_sizes, int n_in,
                              void* d_out, int out_size)
{
    // Identify sigma by size; x/mu order is irrelevant (z.z invariant to sign).
    const float* sigma = nullptr;
    const float* v0 = nullptr;
    const float* v1 = nullptr;
    for (int i = 0; i < n_in; i++) {
        if (in_sizes[i] == NBT * DD * DD) {
            sigma = (const float*)d_in[i];
        } else {
            if (!v0) v0 = (const float*)d_in[i];
            else     v1 = (const float*)d_in[i];
        }
    }

    chol_ll_kernel<<<NBT, 256>>>(v0, v1, sigma);
    reduce_ll_kernel<<<25, 128>>>((float*)d_out);
}

// round 16
// speedup vs baseline: 1.2766x; 1.2766x over previous
#include <cuda_runtime.h>

// Problem constants
#define BB   32
#define TT   400
#define DD   64
#define NBT  (BB*TT)      // 12800 matrices
#define S    68           // shared row stride (floats)
#define NB   8            // Cholesky block size

#define HALF_D_LOG_2PI 58.812066125098784f   // 0.5 * 64 * log(2*pi)
#define EPS 1e-6f

__device__ __align__(16) float g_partial[NBT];
__device__ double g_stage[25];
__device__ int    g_count;     // static-zero; last CTA resets each call

// Trailing-update split per block b: row pairs Pr=(m+1)/2 with m=57-8b trailing
// rows; p = lanes per pair = min(floor(128/Pr), chunks_of_longest_row);
// K = ceil(65536/p) for exact fixed-point tid/p (verified for tid<128).
__constant__ int c_Pr[8] = {29, 25, 21, 17, 13, 9, 5, 1};
__constant__ int c_p [8] = {4, 5, 6, 7, 7, 5, 3, 1};
__constant__ int c_K [8] = {16384, 13108, 10923, 9363, 9363, 13108, 21846, 65536};

// One CTA (128 threads) per matrix. Blocked right-looking Cholesky, NB=8, on the
// bordered 65x64 system (row 64 = x-mu; corner accumulates -z.z).
//
//  sm[66][S] : rows 0..63 sigma (in place), row 64 = border, row 65 = dummy
//              (pair-tail partner; loaded but its results are masked+unstored)
//  Pt[8][S]  : transposed normalized panel, Pt[kk][i] = L[i][b0+kk];
//              Pt[kk][65..67] zeroed so border-row chunk 16 needs no masking.
__global__ __launch_bounds__(128)
void chol_ll_kernel(const float* __restrict__ x,
                    const float* __restrict__ mu,
                    const float* __restrict__ sigma)
{
    __shared__ __align__(16) float sm[66 * S];
    __shared__ __align__(16) float Pt[NB * S];
    __shared__ float wlog[4];

    const int bt   = blockIdx.x;
    const int tid  = threadIdx.x;
    const int lane = tid & 31;
    const int wid  = tid >> 5;

    // ---- Load sigma[bt] (64x64) coalesced via float4 ----
    const float4* src = (const float4*)(sigma + (size_t)bt * (DD * DD));
    #pragma unroll 4
    for (int idx = tid; idx < (DD * DD / 4); idx += 128) {
        float4 v = src[idx];
        int r = idx >> 4;          // row (16 float4 per row)
        int c = (idx & 15) << 2;   // col base
        *(float4*)&sm[r * S + c] = v;
    }
    // ---- Border row 64 = x - mu, corner = 0 ----
    if (tid < DD) sm[64 * S + tid] = x[(size_t)bt * DD + tid] - mu[(size_t)bt * DD + tid];
    if (tid == 64) sm[64 * S + 64] = 0.f;

    float logdet = 0.f;   // per-warp partial (panel rotates across warps)

    #pragma unroll 1
    for (int b = 0; b < 8; b++) {
        const int b0 = b * NB;
        __syncthreads();   // previous trailing update (or load) complete

        // ==== Panel: columns b0..b0+7. Owning warp rotates (b&3) so panel ====
        // ==== issue work spreads across all 4 SMSPs over resident CTAs.  ====
        if (wid == (b & 3)) {
            #pragma unroll
            for (int kk = 0; kk < NB; kk++) {
                const int k = b0 + kk;
                // EPS folded at pivot read (diag accumulates only subtractions
                // before this, so (sigma_kk - S) + EPS == (sigma_kk + EPS) - S)
                float d    = sm[k * S + k] + EPS;
                float invL = rsqrtf(d);
                if (lane == 0) logdet += 0.5f * __logf(d);

                // Normalize column k into Pt[kk][*]
                for (int i = k + 1 + lane; i <= 64; i += 32)
                    Pt[kk * S + i] = sm[i * S + k] * invL;
                if (lane < 3) Pt[kk * S + 65 + lane] = 0.f;  // border-chunk pad
                __syncwarp();

                // Update remaining panel columns j = k+1 .. b0+7
                float s[NB];
                #pragma unroll
                for (int jj = kk + 1; jj < NB; jj++) s[jj] = Pt[kk * S + b0 + jj];
                for (int i = k + 1 + lane; i <= 64; i += 32) {
                    float li = Pt[kk * S + i];
                    #pragma unroll
                    for (int jj = kk + 1; jj < NB; jj++)
                        sm[i * S + b0 + jj] = fmaf(-li, s[jj], sm[i * S + b0 + jj]);
                }
                __syncwarp();
            }
        }
        __syncthreads();   // panel (Pt + panel columns) visible to all warps

        // ==== Rank-8 trailing update: rows lo..64, cols lo..row (float4). ====
        // 2 adjacent rows per thread: Pt chunk loads amortized, 2x FFMA ILP.
        const int lo = b0 + NB;
        const int c0 = lo >> 2;            // 8-aligned cols -> no masking
        const int Pr = c_Pr[b];
        const int p  = c_p[b];
        const int K  = c_K[b];

        if (tid < p * Pr) {
            const int pr = (tid * K) >> 16;   // tid / p (exact fixed-point)
            const int h  = tid - pr * p;
            const int i0 = lo + 2 * pr;
            const int i1 = i0 + 1;
            const bool v1 = (i1 <= 64);       // false only for the (64,65) tail pair

            float Li0[NB], Li1[NB];
            #pragma unroll
            for (int kk = 0; kk < NB; kk++) {
                Li0[kk] = Pt[kk * S + i0];
                Li1[kk] = v1 ? Pt[kk * S + i1] : 0.f;
            }
            const int ce0 = i0 >> 2;          // incl. diagonal chunk (junk above
            const int ce1 = v1 ? (i1 >> 2) : ce0;   //  diag written, never read)
            float* r0 = &sm[i0 * S];
            float* r1 = &sm[i1 * S];          // i1==65 -> dummy row (loads only)

            for (int c = c0 + h; c <= ce1; c += p) {
                float4 a0 = *(float4*)&r0[4 * c];
                float4 a1 = *(float4*)&r1[4 * c];
                #pragma unroll
                for (int kk = 0; kk < NB; kk++) {
                    float4 pk = *(const float4*)&Pt[kk * S + 4 * c];
                    a0.x = fmaf(-Li0[kk], pk.x, a0.x);
                    a0.y = fmaf(-Li0[kk], pk.y, a0.y);
                    a0.z = fmaf(-Li0[kk], pk.z, a0.z);
                    a0.w = fmaf(-Li0[kk], pk.w, a0.w);
                    a1.x = fmaf(-Li1[kk], pk.x, a1.x);
                    a1.y = fmaf(-Li1[kk], pk.y, a1.y);
                    a1.z = fmaf(-Li1[kk], pk.z, a1.z);
                    a1.w = fmaf(-Li1[kk], pk.w, a1.w);
                }
                if (c <= ce0) *(float4*)&r0[4 * c] = a0;
                if (v1)       *(float4*)&r1[4 * c] = a1;
            }
        }
    }

    __syncthreads();
    if (lane == 0) wlog[wid] = logdet;   // every warp owned 2 panels
    __syncthreads();
    if (tid == 0) {
        float ld = wlog[0] + wlog[1] + wlog[2] + wlog[3];
        // sm[64][64] = -diff^T Sigma^{-1} diff
        g_partial[bt] = 0.5f * sm[64 * S + 64] - ld - HALF_D_LOG_2PI;
    }
}

// Single-launch deterministic reduction: 25 CTAs x 512 elems; last CTA (atomic
// ticket) sums the 25 stage values in FIXED order, then resets the ticket.
__global__ __launch_bounds__(128)
void reduce_ll_kernel(float* __restrict__ out)
{
    __shared__ double red[128];
    const float4 v = ((const float4*)g_partial)[blockIdx.x * 128 + threadIdx.x];
    red[threadIdx.x] = (double)v.x + (double)v.y + (double)v.z + (double)v.w;
    __syncthreads();
    #pragma unroll
    for (int s = 64; s > 0; s >>= 1) {
        if (threadIdx.x < s) red[threadIdx.x] += red[threadIdx.x + s];
        __syncthreads();
    }
    if (threadIdx.x == 0) {
        g_stage[blockIdx.x] = red[0];
        __threadfence();
        int done = atomicAdd(&g_count, 1);
        if (done == 24) {
            __threadfence();
            double t = 0.0;
            #pragma unroll
            for (int i = 0; i < 25; i++) t += g_stage[i];
            out[0] = (float)(-t / (double)BB);
            g_count = 0;   // reset for next graph replay
        }
    }
}

extern "C" void kernel_launch(void* const* d_in, const int* in_sizes, int n_in,
                              void* d_out, int out_size)
{
    // Identify sigma by size; x/mu order is irrelevant (z.z invariant to sign).
    const float* sigma = nullptr;
    const float* v0 = nullptr;
    const float* v1 = nullptr;
    for (int i = 0; i < n_in; i++) {
        if (in_sizes[i] == NBT * DD * DD) {
            sigma = (const float*)d_in[i];
        } else {
            if (!v0) v0 = (const float*)d_in[i];
            else     v1 = (const float*)d_in[i];
        }
    }

    chol_ll_kernel<<<NBT, 128>>>(v0, v1, sigma);
    reduce_ll_kernel<<<25, 128>>>((float*)d_out);
}